// round 1
// baseline (speedup 1.0000x reference)
#include <cuda_runtime.h>
#include <math.h>

#define NN 50000
#define NE 800000
#define ETOT 850000      // NE + NN self loops
#define FIN 128
#define D1 128           // NH*HID
#define NH 4
#define HID 32
#define NC 40
#define NEG_SLOPE 0.2f

// ---------------- scratch (device globals; no runtime allocation) ----------------
__device__ __align__(16) float g_h1[NN * D1];        // x @ W1
__device__ __align__(16) float g_esrc1[NN * 4];
__device__ __align__(16) float g_edst1[NN * 4];
__device__ __align__(16) float g_amax1[NN * 4];
__device__ __align__(16) float g_denom1[NN * 4];
__device__ __align__(16) float g_alpha1[ETOT * 4];   // alpha, then exp(alpha-max)
__device__ __align__(16) float g_agg1[NN * D1];      // layer1 aggregate -> ELU in place
__device__ __align__(16) float g_h2[NN * NC];        // h @ W2
__device__ float g_esrc2[NN];
__device__ float g_edst2[NN];
__device__ float g_amax2[NN];
__device__ float g_denom2[NN];
__device__ float g_alpha2[ETOT];
__device__ __align__(16) float g_agg2[NN * NC];

// ---------------- helpers ----------------
__device__ __forceinline__ float lrelu(float v) { return v > 0.0f ? v : NEG_SLOPE * v; }

// float atomic max via signed-max / unsigned-min bit trick (handles negatives, init -inf)
__device__ __forceinline__ void atomicMaxF(float* addr, float v) {
    int b = __float_as_int(v);
    if (b >= 0) atomicMax((int*)addr, b);
    else        atomicMin((unsigned int*)addr, (unsigned int)b);
}

// ---------------- init ----------------
__global__ void init_kernel() {
    int i = blockIdx.x * blockDim.x + threadIdx.x;   // grid covers NN*128 exactly
    g_agg1[i] = 0.0f;
    if (i < NN * NC) g_agg2[i] = 0.0f;
    if (i < NN * 4) { g_denom1[i] = 0.0f; g_amax1[i] = -INFINITY; }
    if (i < NN)     { g_denom2[i] = 0.0f; g_amax2[i] = -INFINITY; }
}

// ---------------- GEMM1: [NN,128] @ [128,128] -> g_h1 ----------------
// block: 256 threads, tile 64 rows x 128 cols, K=128 fully staged (A in smem, W via L1)
__global__ void gemm1_kernel(const float* __restrict__ A, const float* __restrict__ W) {
    __shared__ float As[64][129];
    int tid = threadIdx.x;
    int brow = blockIdx.x * 64;
    // load A tile (64x128)
    #pragma unroll
    for (int p = 0; p < 8; p++) {
        int idx = tid + p * 256;            // 0..2047 float4 slots
        int m = idx >> 5;
        int k4 = (idx & 31) * 4;
        int gr = brow + m;
        float4 v = (gr < NN) ? *(const float4*)(A + (size_t)gr * FIN + k4)
                             : make_float4(0.f, 0.f, 0.f, 0.f);
        As[m][k4 + 0] = v.x; As[m][k4 + 1] = v.y; As[m][k4 + 2] = v.z; As[m][k4 + 3] = v.w;
    }
    __syncthreads();
    int tx = tid & 15, ty = tid >> 4;
    int c0 = tx * 8, r0 = ty * 4;
    float acc[4][8];
    #pragma unroll
    for (int j = 0; j < 4; j++)
        #pragma unroll
        for (int i = 0; i < 8; i++) acc[j][i] = 0.0f;
    #pragma unroll 4
    for (int k = 0; k < 128; k++) {
        float a0 = As[r0][k], a1 = As[r0 + 1][k], a2 = As[r0 + 2][k], a3 = As[r0 + 3][k];
        float4 wa = __ldg((const float4*)(W + k * D1 + c0));
        float4 wb = __ldg((const float4*)(W + k * D1 + c0 + 4));
        float wv[8] = {wa.x, wa.y, wa.z, wa.w, wb.x, wb.y, wb.z, wb.w};
        #pragma unroll
        for (int i = 0; i < 8; i++) {
            acc[0][i] += a0 * wv[i];
            acc[1][i] += a1 * wv[i];
            acc[2][i] += a2 * wv[i];
            acc[3][i] += a3 * wv[i];
        }
    }
    #pragma unroll
    for (int j = 0; j < 4; j++) {
        int row = brow + r0 + j;
        if (row < NN) {
            float* o = g_h1 + (size_t)row * D1 + c0;
            #pragma unroll
            for (int i = 0; i < 8; i++) o[i] = acc[j][i];
        }
    }
}

// ---------------- node attention logits layer 1 (warp per node) ----------------
__global__ void node_e1_kernel(const float* __restrict__ asrc, const float* __restrict__ adst) {
    int warp = (blockIdx.x * blockDim.x + threadIdx.x) >> 5;
    int lane = threadIdx.x & 31;
    if (warp >= NN) return;
    float4 hv = *(const float4*)(g_h1 + (size_t)warp * D1 + lane * 4);
    int h = lane >> 3;
    int off = (lane & 7) * 4;
    float4 as = *(const float4*)(asrc + h * HID + off);
    float4 ad = *(const float4*)(adst + h * HID + off);
    float ps = hv.x * as.x + hv.y * as.y + hv.z * as.z + hv.w * as.w;
    float pd = hv.x * ad.x + hv.y * ad.y + hv.z * ad.z + hv.w * ad.w;
    #pragma unroll
    for (int o = 4; o >= 1; o >>= 1) {
        ps += __shfl_xor_sync(0xffffffffu, ps, o);
        pd += __shfl_xor_sync(0xffffffffu, pd, o);
    }
    if ((lane & 7) == 0) {
        g_esrc1[warp * 4 + h] = ps;
        g_edst1[warp * 4 + h] = pd;
    }
}

// ---------------- edge pass 1: alpha + segment max ----------------
__global__ void edge_alpha_max1_kernel(const int* __restrict__ src, const int* __restrict__ dst) {
    int e = blockIdx.x * blockDim.x + threadIdx.x;
    if (e >= ETOT) return;
    int s, d;
    if (e < NE) { s = src[e]; d = dst[e]; } else { s = d = e - NE; }
    float4 es = *(const float4*)(g_esrc1 + s * 4);
    float4 ed = *(const float4*)(g_edst1 + d * 4);
    float4 a;
    a.x = lrelu(es.x + ed.x); a.y = lrelu(es.y + ed.y);
    a.z = lrelu(es.z + ed.z); a.w = lrelu(es.w + ed.w);
    *(float4*)(g_alpha1 + (size_t)e * 4) = a;
    atomicMaxF(&g_amax1[d * 4 + 0], a.x);
    atomicMaxF(&g_amax1[d * 4 + 1], a.y);
    atomicMaxF(&g_amax1[d * 4 + 2], a.z);
    atomicMaxF(&g_amax1[d * 4 + 3], a.w);
}

// ---------------- edge pass 2: exp + segment sum ----------------
__global__ void edge_exp1_kernel(const int* __restrict__ dst) {
    int e = blockIdx.x * blockDim.x + threadIdx.x;
    if (e >= ETOT) return;
    int d = (e < NE) ? dst[e] : (e - NE);
    float4 a = *(const float4*)(g_alpha1 + (size_t)e * 4);
    float4 m = *(const float4*)(g_amax1 + d * 4);
    float4 ex;
    ex.x = __expf(a.x - m.x); ex.y = __expf(a.y - m.y);
    ex.z = __expf(a.z - m.z); ex.w = __expf(a.w - m.w);
    *(float4*)(g_alpha1 + (size_t)e * 4) = ex;
    atomicAdd(&g_denom1[d * 4 + 0], ex.x);
    atomicAdd(&g_denom1[d * 4 + 1], ex.y);
    atomicAdd(&g_denom1[d * 4 + 2], ex.z);
    atomicAdd(&g_denom1[d * 4 + 3], ex.w);
}

// ---------------- edge pass 3: weighted scatter aggregate (warp per edge) ----------------
__global__ void edge_agg1_kernel(const int* __restrict__ src, const int* __restrict__ dst) {
    int warp = (blockIdx.x * blockDim.x + threadIdx.x) >> 5;
    int lane = threadIdx.x & 31;
    if (warp >= ETOT) return;
    int s, d;
    if (warp < NE) { s = src[warp]; d = dst[warp]; } else { s = d = warp - NE; }
    float4 ex = *(const float4*)(g_alpha1 + (size_t)warp * 4);
    float4 dn = *(const float4*)(g_denom1 + d * 4);
    float4 cf;
    cf.x = ex.x / (dn.x + 1e-16f); cf.y = ex.y / (dn.y + 1e-16f);
    cf.z = ex.z / (dn.z + 1e-16f); cf.w = ex.w / (dn.w + 1e-16f);
    int h = lane >> 3;
    float c = (h == 0) ? cf.x : (h == 1) ? cf.y : (h == 2) ? cf.z : cf.w;
    float4 hv = *(const float4*)(g_h1 + (size_t)s * D1 + lane * 4);
    float* o = g_agg1 + (size_t)d * D1 + lane * 4;
    atomicAdd(o + 0, c * hv.x);
    atomicAdd(o + 1, c * hv.y);
    atomicAdd(o + 2, c * hv.z);
    atomicAdd(o + 3, c * hv.w);
}

// ---------------- bias + ELU (in place on g_agg1) ----------------
__global__ void bias_elu_kernel(const float* __restrict__ bias) {
    int i = blockIdx.x * blockDim.x + threadIdx.x;   // exact NN*128
    float v = g_agg1[i] + bias[i & (D1 - 1)];
    g_agg1[i] = v > 0.0f ? v : (expf(v) - 1.0f);
}

// ---------------- GEMM2: g_agg1 [NN,128] @ W2 [128,40] -> g_h2 ----------------
__global__ void gemm2_kernel(const float* __restrict__ W) {
    __shared__ float As[64][129];
    int tid = threadIdx.x;
    int brow = blockIdx.x * 64;
    #pragma unroll
    for (int p = 0; p < 8; p++) {
        int idx = tid + p * 256;
        int m = idx >> 5;
        int k4 = (idx & 31) * 4;
        int gr = brow + m;
        float4 v = (gr < NN) ? *(const float4*)(g_agg1 + (size_t)gr * D1 + k4)
                             : make_float4(0.f, 0.f, 0.f, 0.f);
        As[m][k4 + 0] = v.x; As[m][k4 + 1] = v.y; As[m][k4 + 2] = v.z; As[m][k4 + 3] = v.w;
    }
    __syncthreads();
    int tx = tid & 7, ty = tid >> 3;      // 8 col groups x 32 row groups
    int c0 = tx * 5, r0 = ty * 2;
    float acc[2][5];
    #pragma unroll
    for (int j = 0; j < 2; j++)
        #pragma unroll
        for (int i = 0; i < 5; i++) acc[j][i] = 0.0f;
    #pragma unroll 4
    for (int k = 0; k < 128; k++) {
        float a0 = As[r0][k], a1 = As[r0 + 1][k];
        #pragma unroll
        for (int i = 0; i < 5; i++) {
            float w = __ldg(W + k * NC + c0 + i);
            acc[0][i] += a0 * w;
            acc[1][i] += a1 * w;
        }
    }
    #pragma unroll
    for (int j = 0; j < 2; j++) {
        int row = brow + r0 + j;
        if (row < NN) {
            float* o = g_h2 + (size_t)row * NC + c0;
            #pragma unroll
            for (int i = 0; i < 5; i++) o[i] = acc[j][i];
        }
    }
}

// ---------------- node attention logits layer 2 (warp per node) ----------------
__global__ void node_e2_kernel(const float* __restrict__ asrc, const float* __restrict__ adst) {
    int warp = (blockIdx.x * blockDim.x + threadIdx.x) >> 5;
    int lane = threadIdx.x & 31;
    if (warp >= NN) return;
    const float* h = g_h2 + (size_t)warp * NC;
    float ps = h[lane] * __ldg(asrc + lane);
    float pd = h[lane] * __ldg(adst + lane);
    if (lane < 8) {
        ps += h[32 + lane] * __ldg(asrc + 32 + lane);
        pd += h[32 + lane] * __ldg(adst + 32 + lane);
    }
    #pragma unroll
    for (int o = 16; o >= 1; o >>= 1) {
        ps += __shfl_xor_sync(0xffffffffu, ps, o);
        pd += __shfl_xor_sync(0xffffffffu, pd, o);
    }
    if (lane == 0) { g_esrc2[warp] = ps; g_edst2[warp] = pd; }
}

__global__ void edge_alpha_max2_kernel(const int* __restrict__ src, const int* __restrict__ dst) {
    int e = blockIdx.x * blockDim.x + threadIdx.x;
    if (e >= ETOT) return;
    int s, d;
    if (e < NE) { s = src[e]; d = dst[e]; } else { s = d = e - NE; }
    float a = lrelu(g_esrc2[s] + g_edst2[d]);
    g_alpha2[e] = a;
    atomicMaxF(&g_amax2[d], a);
}

__global__ void edge_exp2_kernel(const int* __restrict__ dst) {
    int e = blockIdx.x * blockDim.x + threadIdx.x;
    if (e >= ETOT) return;
    int d = (e < NE) ? dst[e] : (e - NE);
    float ex = __expf(g_alpha2[e] - g_amax2[d]);
    g_alpha2[e] = ex;
    atomicAdd(&g_denom2[d], ex);
}

__global__ void edge_agg2_kernel(const int* __restrict__ src, const int* __restrict__ dst) {
    int warp = (blockIdx.x * blockDim.x + threadIdx.x) >> 5;
    int lane = threadIdx.x & 31;
    if (warp >= ETOT) return;
    int s, d;
    if (warp < NE) { s = src[warp]; d = dst[warp]; } else { s = d = warp - NE; }
    float c = g_alpha2[warp] / (g_denom2[d] + 1e-16f);
    const float* h = g_h2 + (size_t)s * NC;
    float* o = g_agg2 + (size_t)d * NC;
    atomicAdd(o + lane, c * h[lane]);
    if (lane < 8) atomicAdd(o + 32 + lane, c * h[32 + lane]);
}

// ---------------- final: bias2 + log_softmax / softmax (warp per node) ----------------
__global__ void final_kernel(const float* __restrict__ bias, float* __restrict__ out) {
    int warp = (blockIdx.x * blockDim.x + threadIdx.x) >> 5;
    int lane = threadIdx.x & 31;
    if (warp >= NN) return;
    const float* a = g_agg2 + (size_t)warp * NC;
    float v0 = a[lane] + __ldg(bias + lane);
    float v1 = (lane < 8) ? (a[32 + lane] + __ldg(bias + 32 + lane)) : -INFINITY;
    float mx = fmaxf(v0, v1);
    #pragma unroll
    for (int o = 16; o >= 1; o >>= 1) mx = fmaxf(mx, __shfl_xor_sync(0xffffffffu, mx, o));
    float e0 = expf(v0 - mx);
    float e1 = (lane < 8) ? expf(v1 - mx) : 0.0f;
    float sm = e0 + e1;
    #pragma unroll
    for (int o = 16; o >= 1; o >>= 1) sm += __shfl_xor_sync(0xffffffffu, sm, o);
    float ls = logf(sm);
    float inv = 1.0f / sm;
    float* lo = out + (size_t)warp * NC;
    float* so = out + (size_t)NN * NC + (size_t)warp * NC;
    lo[lane] = v0 - mx - ls;
    so[lane] = e0 * inv;
    if (lane < 8) {
        lo[32 + lane] = v1 - mx - ls;
        so[32 + lane] = e1 * inv;
    }
}

// ---------------- launch ----------------
extern "C" void kernel_launch(void* const* d_in, const int* in_sizes, int n_in,
                              void* d_out, int out_size) {
    const float* x   = (const float*)d_in[0];
    const int*   ei  = (const int*)d_in[1];
    const float* W1  = (const float*)d_in[2];
    const float* as1 = (const float*)d_in[3];
    const float* ad1 = (const float*)d_in[4];
    const float* b1  = (const float*)d_in[5];
    const float* W2  = (const float*)d_in[6];
    const float* as2 = (const float*)d_in[7];
    const float* ad2 = (const float*)d_in[8];
    const float* b2  = (const float*)d_in[9];
    float* out = (float*)d_out;
    const int* src = ei;
    const int* dst = ei + NE;

    init_kernel<<<25000, 256>>>();
    gemm1_kernel<<<782, 256>>>(x, W1);
    node_e1_kernel<<<6250, 256>>>(as1, ad1);
    edge_alpha_max1_kernel<<<3321, 256>>>(src, dst);
    edge_exp1_kernel<<<3321, 256>>>(dst);
    edge_agg1_kernel<<<106250, 256>>>(src, dst);
    bias_elu_kernel<<<25000, 256>>>(b1);
    gemm2_kernel<<<782, 256>>>(W2);
    node_e2_kernel<<<6250, 256>>>(as2, ad2);
    edge_alpha_max2_kernel<<<3321, 256>>>(src, dst);
    edge_exp2_kernel<<<3321, 256>>>(dst);
    edge_agg2_kernel<<<106250, 256>>>(src, dst);
    final_kernel<<<6250, 256>>>(b2, out);
}

// round 2
// speedup vs baseline: 2.3175x; 2.3175x over previous
#include <cuda_runtime.h>
#include <math.h>

#define NN 50000
#define NE 800000
#define ETOT 850000      // NE + NN self loops
#define FIN 128
#define D1 128           // NH*HID
#define NH 4
#define HID 32
#define NC 40
#define NEG_SLOPE 0.2f
#define NBLK 196         // ceil(NN/256) for scan

// ---------------- scratch (device globals) ----------------
__device__ __align__(16) float g_h1[NN * D1];        // x @ W1
__device__ __align__(16) float g_esrc1[NN * 4];
__device__ __align__(16) float g_edst1[NN * 4];
__device__ __align__(16) float g_agg1[NN * D1];      // layer1 out (bias+ELU applied)
__device__ __align__(16) float g_h2[NN * NC];        // h @ W2
__device__ float g_esrc2[NN];
__device__ float g_edst2[NN];

// CSR build scratch
__device__ int g_cnt[NN];
__device__ int g_scanincl[NN];
__device__ int g_bsum[256];
__device__ int g_rowptr[NN + 1];
__device__ int g_cursor[NN];
__device__ int g_csrc[ETOT];

__device__ __forceinline__ float lrelu(float v) { return v > 0.0f ? v : NEG_SLOPE * v; }

// ---------------- CSR build ----------------
__global__ void init_cnt_kernel() {
    int i = blockIdx.x * blockDim.x + threadIdx.x;
    if (i < NN) g_cnt[i] = 1;   // self loop
}

__global__ void hist_kernel(const int* __restrict__ dst) {
    int e = blockIdx.x * blockDim.x + threadIdx.x;
    if (e < NE) atomicAdd(&g_cnt[dst[e]], 1);
}

__global__ void scan1_kernel() {
    __shared__ int s[256];
    int t = threadIdx.x;
    int i = blockIdx.x * 256 + t;
    int val = (i < NN) ? g_cnt[i] : 0;
    s[t] = val;
    __syncthreads();
    #pragma unroll
    for (int off = 1; off < 256; off <<= 1) {
        int v = (t >= off) ? s[t - off] : 0;
        __syncthreads();
        s[t] += v;
        __syncthreads();
    }
    if (i < NN) g_scanincl[i] = s[t];
    if (t == 255) g_bsum[blockIdx.x] = s[255];
}

__global__ void scan2_kernel() {
    __shared__ int s[256];
    int t = threadIdx.x;
    int val = (t < NBLK) ? g_bsum[t] : 0;
    s[t] = val;
    __syncthreads();
    #pragma unroll
    for (int off = 1; off < 256; off <<= 1) {
        int v = (t >= off) ? s[t - off] : 0;
        __syncthreads();
        s[t] += v;
        __syncthreads();
    }
    g_bsum[t] = s[t] - val;   // exclusive
}

__global__ void scan3_kernel() {
    int i = blockIdx.x * blockDim.x + threadIdx.x;
    if (i < NN) {
        int rp = g_scanincl[i] - g_cnt[i] + g_bsum[i >> 8];
        g_rowptr[i] = rp;
        g_cursor[i] = rp;
    }
    if (i == NN) g_rowptr[NN] = ETOT;
}

__global__ void place_kernel(const int* __restrict__ src, const int* __restrict__ dst) {
    int e = blockIdx.x * blockDim.x + threadIdx.x;
    if (e >= ETOT) return;
    int s, d;
    if (e < NE) { s = src[e]; d = dst[e]; } else { s = d = e - NE; }
    int pos = atomicAdd(&g_cursor[d], 1);
    g_csrc[pos] = s;
}

// ---------------- GEMM1: [NN,128] @ [128,128] -> g_h1 ----------------
__global__ void gemm1_kernel(const float* __restrict__ A, const float* __restrict__ W) {
    __shared__ float As[64][129];
    int tid = threadIdx.x;
    int brow = blockIdx.x * 64;
    #pragma unroll
    for (int p = 0; p < 8; p++) {
        int idx = tid + p * 256;
        int m = idx >> 5;
        int k4 = (idx & 31) * 4;
        int gr = brow + m;
        float4 v = (gr < NN) ? *(const float4*)(A + (size_t)gr * FIN + k4)
                             : make_float4(0.f, 0.f, 0.f, 0.f);
        As[m][k4 + 0] = v.x; As[m][k4 + 1] = v.y; As[m][k4 + 2] = v.z; As[m][k4 + 3] = v.w;
    }
    __syncthreads();
    int tx = tid & 15, ty = tid >> 4;
    int c0 = tx * 8, r0 = ty * 4;
    float acc[4][8];
    #pragma unroll
    for (int j = 0; j < 4; j++)
        #pragma unroll
        for (int i = 0; i < 8; i++) acc[j][i] = 0.0f;
    #pragma unroll 4
    for (int k = 0; k < 128; k++) {
        float a0 = As[r0][k], a1 = As[r0 + 1][k], a2 = As[r0 + 2][k], a3 = As[r0 + 3][k];
        float4 wa = __ldg((const float4*)(W + k * D1 + c0));
        float4 wb = __ldg((const float4*)(W + k * D1 + c0 + 4));
        float wv[8] = {wa.x, wa.y, wa.z, wa.w, wb.x, wb.y, wb.z, wb.w};
        #pragma unroll
        for (int i = 0; i < 8; i++) {
            acc[0][i] += a0 * wv[i];
            acc[1][i] += a1 * wv[i];
            acc[2][i] += a2 * wv[i];
            acc[3][i] += a3 * wv[i];
        }
    }
    #pragma unroll
    for (int j = 0; j < 4; j++) {
        int row = brow + r0 + j;
        if (row < NN) {
            float* o = g_h1 + (size_t)row * D1 + c0;
            #pragma unroll
            for (int i = 0; i < 8; i++) o[i] = acc[j][i];
        }
    }
}

// ---------------- node attention logits layer 1 (warp per node) ----------------
__global__ void node_e1_kernel(const float* __restrict__ asrc, const float* __restrict__ adst) {
    int warp = (blockIdx.x * blockDim.x + threadIdx.x) >> 5;
    int lane = threadIdx.x & 31;
    if (warp >= NN) return;
    float4 hv = *(const float4*)(g_h1 + (size_t)warp * D1 + lane * 4);
    int h = lane >> 3;
    int off = (lane & 7) * 4;
    float4 as = *(const float4*)(asrc + h * HID + off);
    float4 ad = *(const float4*)(adst + h * HID + off);
    float ps = hv.x * as.x + hv.y * as.y + hv.z * as.z + hv.w * as.w;
    float pd = hv.x * ad.x + hv.y * ad.y + hv.z * ad.z + hv.w * ad.w;
    #pragma unroll
    for (int o = 4; o >= 1; o >>= 1) {
        ps += __shfl_xor_sync(0xffffffffu, ps, o);
        pd += __shfl_xor_sync(0xffffffffu, pd, o);
    }
    if ((lane & 7) == 0) {
        g_esrc1[warp * 4 + h] = ps;
        g_edst1[warp * 4 + h] = pd;
    }
}

// ---------------- fused GAT layer 1: softmax + aggregate + bias + ELU ----------------
__global__ void gat1_kernel(const float* __restrict__ bias) {
    int warp = (blockIdx.x * blockDim.x + threadIdx.x) >> 5;
    int lane = threadIdx.x & 31;
    if (warp >= NN) return;
    int d = warp;
    int base = g_rowptr[d];
    int end  = g_rowptr[d + 1];
    int h = lane >> 3;
    float4 ed4 = *(const float4*)(g_edst1 + d * 4);

    // phase 1: per-head max
    float4 mx4 = make_float4(-INFINITY, -INFINITY, -INFINITY, -INFINITY);
    for (int j = base + lane; j < end; j += 32) {
        int s = g_csrc[j];
        float4 es = *(const float4*)(g_esrc1 + s * 4);
        mx4.x = fmaxf(mx4.x, lrelu(es.x + ed4.x));
        mx4.y = fmaxf(mx4.y, lrelu(es.y + ed4.y));
        mx4.z = fmaxf(mx4.z, lrelu(es.z + ed4.z));
        mx4.w = fmaxf(mx4.w, lrelu(es.w + ed4.w));
    }
    #pragma unroll
    for (int o = 16; o >= 1; o >>= 1) {
        mx4.x = fmaxf(mx4.x, __shfl_xor_sync(0xffffffffu, mx4.x, o));
        mx4.y = fmaxf(mx4.y, __shfl_xor_sync(0xffffffffu, mx4.y, o));
        mx4.z = fmaxf(mx4.z, __shfl_xor_sync(0xffffffffu, mx4.z, o));
        mx4.w = fmaxf(mx4.w, __shfl_xor_sync(0xffffffffu, mx4.w, o));
    }
    // phase 2: per-head denom
    float4 sm4 = make_float4(0.f, 0.f, 0.f, 0.f);
    for (int j = base + lane; j < end; j += 32) {
        int s = g_csrc[j];
        float4 es = *(const float4*)(g_esrc1 + s * 4);
        sm4.x += __expf(lrelu(es.x + ed4.x) - mx4.x);
        sm4.y += __expf(lrelu(es.y + ed4.y) - mx4.y);
        sm4.z += __expf(lrelu(es.z + ed4.z) - mx4.z);
        sm4.w += __expf(lrelu(es.w + ed4.w) - mx4.w);
    }
    #pragma unroll
    for (int o = 16; o >= 1; o >>= 1) {
        sm4.x += __shfl_xor_sync(0xffffffffu, sm4.x, o);
        sm4.y += __shfl_xor_sync(0xffffffffu, sm4.y, o);
        sm4.z += __shfl_xor_sync(0xffffffffu, sm4.z, o);
        sm4.w += __shfl_xor_sync(0xffffffffu, sm4.w, o);
    }
    float mx = (h == 0) ? mx4.x : (h == 1) ? mx4.y : (h == 2) ? mx4.z : mx4.w;
    float dn = (h == 0) ? sm4.x : (h == 1) ? sm4.y : (h == 2) ? sm4.z : sm4.w;
    float inv = 1.0f / (dn + 1e-16f);
    float ed_h = (h == 0) ? ed4.x : (h == 1) ? ed4.y : (h == 2) ? ed4.z : ed4.w;

    // phase 3: weighted gather-aggregate (unroll x2 for MLP)
    float4 acc = make_float4(0.f, 0.f, 0.f, 0.f);
    float4 acc2 = make_float4(0.f, 0.f, 0.f, 0.f);
    int j = base;
    for (; j + 1 < end; j += 2) {
        int s0 = g_csrc[j];
        int s1 = g_csrc[j + 1];
        float es0 = g_esrc1[s0 * 4 + h];
        float es1 = g_esrc1[s1 * 4 + h];
        float4 f0 = *(const float4*)(g_h1 + (size_t)s0 * D1 + lane * 4);
        float4 f1 = *(const float4*)(g_h1 + (size_t)s1 * D1 + lane * 4);
        float c0 = __expf(lrelu(es0 + ed_h) - mx) * inv;
        float c1 = __expf(lrelu(es1 + ed_h) - mx) * inv;
        acc.x += c0 * f0.x; acc.y += c0 * f0.y; acc.z += c0 * f0.z; acc.w += c0 * f0.w;
        acc2.x += c1 * f1.x; acc2.y += c1 * f1.y; acc2.z += c1 * f1.z; acc2.w += c1 * f1.w;
    }
    if (j < end) {
        int s0 = g_csrc[j];
        float es0 = g_esrc1[s0 * 4 + h];
        float4 f0 = *(const float4*)(g_h1 + (size_t)s0 * D1 + lane * 4);
        float c0 = __expf(lrelu(es0 + ed_h) - mx) * inv;
        acc.x += c0 * f0.x; acc.y += c0 * f0.y; acc.z += c0 * f0.z; acc.w += c0 * f0.w;
    }
    acc.x += acc2.x; acc.y += acc2.y; acc.z += acc2.z; acc.w += acc2.w;

    // bias + ELU
    float4 b = *(const float4*)(bias + lane * 4);
    float4 v;
    v.x = acc.x + b.x; v.y = acc.y + b.y; v.z = acc.z + b.z; v.w = acc.w + b.w;
    v.x = v.x > 0.f ? v.x : (__expf(v.x) - 1.f);
    v.y = v.y > 0.f ? v.y : (__expf(v.y) - 1.f);
    v.z = v.z > 0.f ? v.z : (__expf(v.z) - 1.f);
    v.w = v.w > 0.f ? v.w : (__expf(v.w) - 1.f);
    *(float4*)(g_agg1 + (size_t)d * D1 + lane * 4) = v;
}

// ---------------- GEMM2: g_agg1 [NN,128] @ W2 [128,40] -> g_h2 ----------------
__global__ void gemm2_kernel(const float* __restrict__ W) {
    __shared__ float As[64][129];
    int tid = threadIdx.x;
    int brow = blockIdx.x * 64;
    #pragma unroll
    for (int p = 0; p < 8; p++) {
        int idx = tid + p * 256;
        int m = idx >> 5;
        int k4 = (idx & 31) * 4;
        int gr = brow + m;
        float4 v = (gr < NN) ? *(const float4*)(g_agg1 + (size_t)gr * D1 + k4)
                             : make_float4(0.f, 0.f, 0.f, 0.f);
        As[m][k4 + 0] = v.x; As[m][k4 + 1] = v.y; As[m][k4 + 2] = v.z; As[m][k4 + 3] = v.w;
    }
    __syncthreads();
    int tx = tid & 7, ty = tid >> 3;
    int c0 = tx * 5, r0 = ty * 2;
    float acc[2][5];
    #pragma unroll
    for (int j = 0; j < 2; j++)
        #pragma unroll
        for (int i = 0; i < 5; i++) acc[j][i] = 0.0f;
    #pragma unroll 4
    for (int k = 0; k < 128; k++) {
        float a0 = As[r0][k], a1 = As[r0 + 1][k];
        #pragma unroll
        for (int i = 0; i < 5; i++) {
            float w = __ldg(W + k * NC + c0 + i);
            acc[0][i] += a0 * w;
            acc[1][i] += a1 * w;
        }
    }
    #pragma unroll
    for (int j = 0; j < 2; j++) {
        int row = brow + r0 + j;
        if (row < NN) {
            float* o = g_h2 + (size_t)row * NC + c0;
            #pragma unroll
            for (int i = 0; i < 5; i++) o[i] = acc[j][i];
        }
    }
}

// ---------------- node attention logits layer 2 ----------------
__global__ void node_e2_kernel(const float* __restrict__ asrc, const float* __restrict__ adst) {
    int warp = (blockIdx.x * blockDim.x + threadIdx.x) >> 5;
    int lane = threadIdx.x & 31;
    if (warp >= NN) return;
    const float* hp = g_h2 + (size_t)warp * NC;
    float ps = hp[lane] * __ldg(asrc + lane);
    float pd = hp[lane] * __ldg(adst + lane);
    if (lane < 8) {
        ps += hp[32 + lane] * __ldg(asrc + 32 + lane);
        pd += hp[32 + lane] * __ldg(adst + 32 + lane);
    }
    #pragma unroll
    for (int o = 16; o >= 1; o >>= 1) {
        ps += __shfl_xor_sync(0xffffffffu, ps, o);
        pd += __shfl_xor_sync(0xffffffffu, pd, o);
    }
    if (lane == 0) { g_esrc2[warp] = ps; g_edst2[warp] = pd; }
}

// ---------------- fused GAT layer 2 + bias + log_softmax/softmax ----------------
__global__ void gat2_kernel(const float* __restrict__ bias, float* __restrict__ out) {
    int warp = (blockIdx.x * blockDim.x + threadIdx.x) >> 5;
    int lane = threadIdx.x & 31;
    if (warp >= NN) return;
    int d = warp;
    int base = g_rowptr[d];
    int end  = g_rowptr[d + 1];
    float ed = g_edst2[d];

    // phase 1: max
    float mx = -INFINITY;
    for (int j = base + lane; j < end; j += 32)
        mx = fmaxf(mx, lrelu(g_esrc2[g_csrc[j]] + ed));
    #pragma unroll
    for (int o = 16; o >= 1; o >>= 1) mx = fmaxf(mx, __shfl_xor_sync(0xffffffffu, mx, o));
    // phase 2: denom
    float dn = 0.f;
    for (int j = base + lane; j < end; j += 32)
        dn += __expf(lrelu(g_esrc2[g_csrc[j]] + ed) - mx);
    #pragma unroll
    for (int o = 16; o >= 1; o >>= 1) dn += __shfl_xor_sync(0xffffffffu, dn, o);
    float inv = 1.0f / (dn + 1e-16f);

    // phase 3: weighted gather
    float acc0 = 0.f, acc1 = 0.f;
    float acc0b = 0.f, acc1b = 0.f;
    int j = base;
    for (; j + 1 < end; j += 2) {
        int s0 = g_csrc[j];
        int s1 = g_csrc[j + 1];
        float es0 = g_esrc2[s0];
        float es1 = g_esrc2[s1];
        const float* h0 = g_h2 + (size_t)s0 * NC;
        const float* h1p = g_h2 + (size_t)s1 * NC;
        float f00 = h0[lane];
        float f10 = h1p[lane];
        float f01 = (lane < 8) ? h0[32 + lane] : 0.f;
        float f11 = (lane < 8) ? h1p[32 + lane] : 0.f;
        float c0 = __expf(lrelu(es0 + ed) - mx) * inv;
        float c1 = __expf(lrelu(es1 + ed) - mx) * inv;
        acc0 += c0 * f00; acc1 += c0 * f01;
        acc0b += c1 * f10; acc1b += c1 * f11;
    }
    if (j < end) {
        int s0 = g_csrc[j];
        float es0 = g_esrc2[s0];
        const float* h0 = g_h2 + (size_t)s0 * NC;
        float c0 = __expf(lrelu(es0 + ed) - mx) * inv;
        acc0 += c0 * h0[lane];
        if (lane < 8) acc1 += c0 * h0[32 + lane];
    }
    acc0 += acc0b; acc1 += acc1b;

    // bias + softmax / log_softmax
    float v0 = acc0 + __ldg(bias + lane);
    float v1 = (lane < 8) ? (acc1 + __ldg(bias + 32 + lane)) : -INFINITY;
    float m = fmaxf(v0, v1);
    #pragma unroll
    for (int o = 16; o >= 1; o >>= 1) m = fmaxf(m, __shfl_xor_sync(0xffffffffu, m, o));
    float e0 = expf(v0 - m);
    float e1 = (lane < 8) ? expf(v1 - m) : 0.f;
    float sm = e0 + e1;
    #pragma unroll
    for (int o = 16; o >= 1; o >>= 1) sm += __shfl_xor_sync(0xffffffffu, sm, o);
    float ls = logf(sm);
    float invs = 1.0f / sm;
    float* lo = out + (size_t)d * NC;
    float* so = out + (size_t)NN * NC + (size_t)d * NC;
    lo[lane] = v0 - m - ls;
    so[lane] = e0 * invs;
    if (lane < 8) {
        lo[32 + lane] = v1 - m - ls;
        so[32 + lane] = e1 * invs;
    }
}

// ---------------- launch ----------------
extern "C" void kernel_launch(void* const* d_in, const int* in_sizes, int n_in,
                              void* d_out, int out_size) {
    const float* x   = (const float*)d_in[0];
    const int*   ei  = (const int*)d_in[1];
    const float* W1  = (const float*)d_in[2];
    const float* as1 = (const float*)d_in[3];
    const float* ad1 = (const float*)d_in[4];
    const float* b1  = (const float*)d_in[5];
    const float* W2  = (const float*)d_in[6];
    const float* as2 = (const float*)d_in[7];
    const float* ad2 = (const float*)d_in[8];
    const float* b2  = (const float*)d_in[9];
    float* out = (float*)d_out;
    const int* src = ei;
    const int* dst = ei + NE;

    // CSR build (overlaps nothing; stream-serial)
    init_cnt_kernel<<<NBLK, 256>>>();
    hist_kernel<<<3125, 256>>>(dst);
    scan1_kernel<<<NBLK, 256>>>();
    scan2_kernel<<<1, 256>>>();
    scan3_kernel<<<NBLK + 1, 256>>>();
    place_kernel<<<3321, 256>>>(src, dst);

    gemm1_kernel<<<782, 256>>>(x, W1);
    node_e1_kernel<<<6250, 256>>>(as1, ad1);
    gat1_kernel<<<6250, 256>>>(b1);
    gemm2_kernel<<<782, 256>>>(W2);
    node_e2_kernel<<<6250, 256>>>(as2, ad2);
    gat2_kernel<<<6250, 256>>>(b2, out);
}

// round 3
// speedup vs baseline: 2.4620x; 1.0624x over previous
#include <cuda_runtime.h>
#include <math.h>

#define NN 50000
#define NE 800000
#define ETOT 850000      // NE + NN self loops
#define FIN 128
#define D1 128           // NH*HID
#define NH 4
#define HID 32
#define NC 40
#define NEG_SLOPE 0.2f
#define NBLK 196         // ceil(NN/256)

// ---------------- scratch (device globals) ----------------
__device__ __align__(16) float g_h1[NN * D1];        // x @ W1
__device__ __align__(16) float g_esrc1[NN * 4];
__device__ __align__(16) float g_edst1[NN * 4];
__device__ __align__(16) float g_agg1[NN * D1];      // layer1 out (bias+ELU applied)
__device__ __align__(16) float g_h2[NN * NC];        // h @ W2
__device__ float g_esrc2[NN];
__device__ float g_edst2[NN];

// CSR build scratch. g_cnt is zeroed by gat2_kernel at the END of each
// invocation (and is zero-initialized at load), so hist can atomically add
// without an init kernel.
__device__ int g_cnt[NN];
__device__ int g_scanincl[NN];
__device__ int g_bsum[NBLK];
__device__ int g_rowptr[NN + 1];
__device__ int g_cursor[NN];
__device__ int g_csrc[ETOT];

__device__ __forceinline__ float lrelu(float v) { return v > 0.0f ? v : NEG_SLOPE * v; }

// ---------------- CSR build ----------------
__global__ void hist_kernel(const int* __restrict__ dst) {
    int e = blockIdx.x * blockDim.x + threadIdx.x;
    if (e < NE) atomicAdd(&g_cnt[dst[e]], 1);
}

// inclusive scan of (cnt[i]+1) within each block; block totals to g_bsum
__global__ void scan1_kernel() {
    __shared__ int s[256];
    int t = threadIdx.x;
    int i = blockIdx.x * 256 + t;
    int val = (i < NN) ? (g_cnt[i] + 1) : 0;
    s[t] = val;
    __syncthreads();
    #pragma unroll
    for (int off = 1; off < 256; off <<= 1) {
        int v = (t >= off) ? s[t - off] : 0;
        __syncthreads();
        s[t] += v;
        __syncthreads();
    }
    if (i < NN) g_scanincl[i] = s[t];
    if (t == 255) g_bsum[blockIdx.x] = s[255];
}

// per-block prefix over g_bsum computed in-kernel; emit rowptr, cursor, self-loop
__global__ void scan3_kernel() {
    __shared__ int wsum[8];
    int t = threadIdx.x;
    int b = blockIdx.x;
    int lane = t & 31;
    int v = (t < b && t < NBLK) ? g_bsum[t] : 0;
    #pragma unroll
    for (int o = 16; o >= 1; o >>= 1) v += __shfl_xor_sync(0xffffffffu, v, o);
    if (lane == 0) wsum[t >> 5] = v;
    __syncthreads();
    int prefix = wsum[0] + wsum[1] + wsum[2] + wsum[3] + wsum[4] + wsum[5] + wsum[6] + wsum[7];
    int i = b * 256 + t;
    if (i < NN) {
        int rp = g_scanincl[i] - (g_cnt[i] + 1) + prefix;
        g_rowptr[i] = rp;
        g_csrc[rp] = i;          // self loop occupies slot 0 of each row
        g_cursor[i] = rp + 1;
    }
    if (i == NN) g_rowptr[NN] = ETOT;
}

__global__ void place_kernel(const int* __restrict__ src, const int* __restrict__ dst) {
    int e = blockIdx.x * blockDim.x + threadIdx.x;
    if (e >= NE) return;
    int pos = atomicAdd(&g_cursor[dst[e]], 1);
    g_csrc[pos] = src[e];
}

// ---------------- GEMM1 + node attention logits epilogue ----------------
__global__ void gemm1_kernel(const float* __restrict__ A, const float* __restrict__ W,
                             const float* __restrict__ asrc, const float* __restrict__ adst) {
    __shared__ float As[64][132];
    int tid = threadIdx.x;
    int brow = blockIdx.x * 64;
    #pragma unroll
    for (int p = 0; p < 8; p++) {
        int idx = tid + p * 256;
        int m = idx >> 5;
        int k4 = (idx & 31) * 4;
        int gr = brow + m;
        float4 v = (gr < NN) ? *(const float4*)(A + (size_t)gr * FIN + k4)
                             : make_float4(0.f, 0.f, 0.f, 0.f);
        As[m][k4 + 0] = v.x; As[m][k4 + 1] = v.y; As[m][k4 + 2] = v.z; As[m][k4 + 3] = v.w;
    }
    __syncthreads();
    int tx = tid & 15, ty = tid >> 4;
    int c0 = tx * 8, r0 = ty * 4;
    float acc[4][8];
    #pragma unroll
    for (int j = 0; j < 4; j++)
        #pragma unroll
        for (int i = 0; i < 8; i++) acc[j][i] = 0.0f;
    #pragma unroll 4
    for (int k = 0; k < 128; k++) {
        float a0 = As[r0][k], a1 = As[r0 + 1][k], a2 = As[r0 + 2][k], a3 = As[r0 + 3][k];
        float4 wa = __ldg((const float4*)(W + k * D1 + c0));
        float4 wb = __ldg((const float4*)(W + k * D1 + c0 + 4));
        float wv[8] = {wa.x, wa.y, wa.z, wa.w, wb.x, wb.y, wb.z, wb.w};
        #pragma unroll
        for (int i = 0; i < 8; i++) {
            acc[0][i] += a0 * wv[i];
            acc[1][i] += a1 * wv[i];
            acc[2][i] += a2 * wv[i];
            acc[3][i] += a3 * wv[i];
        }
    }
    // write h1 to global
    #pragma unroll
    for (int j = 0; j < 4; j++) {
        int row = brow + r0 + j;
        if (row < NN) {
            float* o = g_h1 + (size_t)row * D1 + c0;
            #pragma unroll
            for (int i = 0; i < 8; i++) o[i] = acc[j][i];
        }
    }
    // stage tile into smem for attention-logit epilogue
    __syncthreads();
    #pragma unroll
    for (int j = 0; j < 4; j++)
        #pragma unroll
        for (int i = 0; i < 8; i++) As[r0 + j][c0 + i] = acc[j][i];
    __syncthreads();
    // 8 warps x 8 rows: e_src/e_dst per head
    int wid = tid >> 5, lane = tid & 31;
    int h = lane >> 3;
    int off = (lane & 7) * 4;
    float4 a4 = *(const float4*)(asrc + h * HID + off);
    float4 d4 = *(const float4*)(adst + h * HID + off);
    #pragma unroll
    for (int rr = 0; rr < 8; rr++) {
        int row = wid * 8 + rr;
        int grow = brow + row;
        float4 hv = *(const float4*)(&As[row][lane * 4]);
        float ps = hv.x * a4.x + hv.y * a4.y + hv.z * a4.z + hv.w * a4.w;
        float pd = hv.x * d4.x + hv.y * d4.y + hv.z * d4.z + hv.w * d4.w;
        #pragma unroll
        for (int o = 4; o >= 1; o >>= 1) {
            ps += __shfl_xor_sync(0xffffffffu, ps, o);
            pd += __shfl_xor_sync(0xffffffffu, pd, o);
        }
        if ((lane & 7) == 0 && grow < NN) {
            g_esrc1[grow * 4 + h] = ps;
            g_edst1[grow * 4 + h] = pd;
        }
    }
}

// ---------------- fused GAT layer 1: online softmax + aggregate + bias + ELU ----------------
__global__ void gat1_kernel(const float* __restrict__ bias) {
    int warp = (blockIdx.x * blockDim.x + threadIdx.x) >> 5;
    int lane = threadIdx.x & 31;
    if (warp >= NN) return;
    int d = warp;
    int base = g_rowptr[d];
    int end  = g_rowptr[d + 1];
    int h = lane >> 3;
    float ed_h = g_edst1[d * 4 + h];

    float mxA = -INFINITY, smA = 0.f;
    float mxB = -INFINITY, smB = 0.f;
    float4 accA = make_float4(0.f, 0.f, 0.f, 0.f);
    float4 accB = make_float4(0.f, 0.f, 0.f, 0.f);
    int j = base;
    for (; j + 1 < end; j += 2) {
        int s0 = g_csrc[j];
        int s1 = g_csrc[j + 1];
        float es0 = g_esrc1[s0 * 4 + h];
        float es1 = g_esrc1[s1 * 4 + h];
        float4 f0 = *(const float4*)(g_h1 + (size_t)s0 * D1 + lane * 4);
        float4 f1 = *(const float4*)(g_h1 + (size_t)s1 * D1 + lane * 4);
        float a0 = lrelu(es0 + ed_h);
        float a1 = lrelu(es1 + ed_h);
        float nmA = fmaxf(mxA, a0);
        float scA = __expf(mxA - nmA);
        float w0  = __expf(a0 - nmA);
        smA = smA * scA + w0;
        accA.x = accA.x * scA + w0 * f0.x;
        accA.y = accA.y * scA + w0 * f0.y;
        accA.z = accA.z * scA + w0 * f0.z;
        accA.w = accA.w * scA + w0 * f0.w;
        mxA = nmA;
        float nmB = fmaxf(mxB, a1);
        float scB = __expf(mxB - nmB);
        float w1  = __expf(a1 - nmB);
        smB = smB * scB + w1;
        accB.x = accB.x * scB + w1 * f1.x;
        accB.y = accB.y * scB + w1 * f1.y;
        accB.z = accB.z * scB + w1 * f1.z;
        accB.w = accB.w * scB + w1 * f1.w;
        mxB = nmB;
    }
    if (j < end) {
        int s0 = g_csrc[j];
        float es0 = g_esrc1[s0 * 4 + h];
        float4 f0 = *(const float4*)(g_h1 + (size_t)s0 * D1 + lane * 4);
        float a0 = lrelu(es0 + ed_h);
        float nmA = fmaxf(mxA, a0);
        float scA = __expf(mxA - nmA);
        float w0  = __expf(a0 - nmA);
        smA = smA * scA + w0;
        accA.x = accA.x * scA + w0 * f0.x;
        accA.y = accA.y * scA + w0 * f0.y;
        accA.z = accA.z * scA + w0 * f0.z;
        accA.w = accA.w * scA + w0 * f0.w;
        mxA = nmA;
    }
    // merge A/B states
    float nm = fmaxf(mxA, mxB);
    float sA = __expf(mxA - nm);
    float sB = __expf(mxB - nm);
    float sum = smA * sA + smB * sB;
    float4 acc;
    acc.x = accA.x * sA + accB.x * sB;
    acc.y = accA.y * sA + accB.y * sB;
    acc.z = accA.z * sA + accB.z * sB;
    acc.w = accA.w * sA + accB.w * sB;
    float inv = 1.0f / (sum + 1e-16f);

    float4 b = *(const float4*)(bias + lane * 4);
    float4 v;
    v.x = acc.x * inv + b.x; v.y = acc.y * inv + b.y;
    v.z = acc.z * inv + b.z; v.w = acc.w * inv + b.w;
    v.x = v.x > 0.f ? v.x : (__expf(v.x) - 1.f);
    v.y = v.y > 0.f ? v.y : (__expf(v.y) - 1.f);
    v.z = v.z > 0.f ? v.z : (__expf(v.z) - 1.f);
    v.w = v.w > 0.f ? v.w : (__expf(v.w) - 1.f);
    *(float4*)(g_agg1 + (size_t)d * D1 + lane * 4) = v;
}

// ---------------- GEMM2 + node attention logits epilogue ----------------
__global__ void gemm2_kernel(const float* __restrict__ W,
                             const float* __restrict__ asrc, const float* __restrict__ adst) {
    __shared__ float As[64][132];
    int tid = threadIdx.x;
    int brow = blockIdx.x * 64;
    #pragma unroll
    for (int p = 0; p < 8; p++) {
        int idx = tid + p * 256;
        int m = idx >> 5;
        int k4 = (idx & 31) * 4;
        int gr = brow + m;
        float4 v = (gr < NN) ? *(const float4*)(g_agg1 + (size_t)gr * D1 + k4)
                             : make_float4(0.f, 0.f, 0.f, 0.f);
        As[m][k4 + 0] = v.x; As[m][k4 + 1] = v.y; As[m][k4 + 2] = v.z; As[m][k4 + 3] = v.w;
    }
    __syncthreads();
    int tx = tid & 7, ty = tid >> 3;
    int c0 = tx * 5, r0 = ty * 2;
    float acc[2][5];
    #pragma unroll
    for (int j = 0; j < 2; j++)
        #pragma unroll
        for (int i = 0; i < 5; i++) acc[j][i] = 0.0f;
    #pragma unroll 4
    for (int k = 0; k < 128; k++) {
        float a0 = As[r0][k], a1 = As[r0 + 1][k];
        #pragma unroll
        for (int i = 0; i < 5; i++) {
            float w = __ldg(W + k * NC + c0 + i);
            acc[0][i] += a0 * w;
            acc[1][i] += a1 * w;
        }
    }
    #pragma unroll
    for (int j = 0; j < 2; j++) {
        int row = brow + r0 + j;
        if (row < NN) {
            float* o = g_h2 + (size_t)row * NC + c0;
            #pragma unroll
            for (int i = 0; i < 5; i++) o[i] = acc[j][i];
        }
    }
    // stage h2 tile into smem for logit epilogue
    __syncthreads();
    #pragma unroll
    for (int j = 0; j < 2; j++)
        #pragma unroll
        for (int i = 0; i < 5; i++) As[r0 + j][c0 + i] = acc[j][i];
    __syncthreads();
    int wid = tid >> 5, lane = tid & 31;
    float a_lo = __ldg(asrc + lane);
    float d_lo = __ldg(adst + lane);
    float a_hi = (lane < 8) ? __ldg(asrc + 32 + lane) : 0.f;
    float d_hi = (lane < 8) ? __ldg(adst + 32 + lane) : 0.f;
    #pragma unroll
    for (int rr = 0; rr < 8; rr++) {
        int row = wid * 8 + rr;
        int grow = brow + row;
        float v0 = As[row][lane];
        float v1 = (lane < 8) ? As[row][32 + lane] : 0.f;
        float ps = v0 * a_lo + v1 * a_hi;
        float pd = v0 * d_lo + v1 * d_hi;
        #pragma unroll
        for (int o = 16; o >= 1; o >>= 1) {
            ps += __shfl_xor_sync(0xffffffffu, ps, o);
            pd += __shfl_xor_sync(0xffffffffu, pd, o);
        }
        if (lane == 0 && grow < NN) {
            g_esrc2[grow] = ps;
            g_edst2[grow] = pd;
        }
    }
}

// ---------------- fused GAT layer 2: online softmax + aggregate + bias + log_softmax/softmax ----------------
__global__ void gat2_kernel(const float* __restrict__ bias, float* __restrict__ out) {
    int warp = (blockIdx.x * blockDim.x + threadIdx.x) >> 5;
    int lane = threadIdx.x & 31;
    if (warp >= NN) return;
    int d = warp;
    if (lane == 0) g_cnt[d] = 0;   // reset histogram for the NEXT invocation
    int base = g_rowptr[d];
    int end  = g_rowptr[d + 1];
    float ed = g_edst2[d];

    float mxA = -INFINITY, smA = 0.f, a0A = 0.f, a1A = 0.f;
    float mxB = -INFINITY, smB = 0.f, a0B = 0.f, a1B = 0.f;
    int j = base;
    for (; j + 1 < end; j += 2) {
        int s0 = g_csrc[j];
        int s1 = g_csrc[j + 1];
        float es0 = g_esrc2[s0];
        float es1 = g_esrc2[s1];
        const float* h0 = g_h2 + (size_t)s0 * NC;
        const float* h1p = g_h2 + (size_t)s1 * NC;
        float f00 = h0[lane];
        float f10 = h1p[lane];
        float f01 = (lane < 8) ? h0[32 + lane] : 0.f;
        float f11 = (lane < 8) ? h1p[32 + lane] : 0.f;
        float aa = lrelu(es0 + ed);
        float ab = lrelu(es1 + ed);
        float nmA = fmaxf(mxA, aa);
        float scA = __expf(mxA - nmA);
        float w0  = __expf(aa - nmA);
        smA = smA * scA + w0;
        a0A = a0A * scA + w0 * f00;
        a1A = a1A * scA + w0 * f01;
        mxA = nmA;
        float nmB = fmaxf(mxB, ab);
        float scB = __expf(mxB - nmB);
        float w1  = __expf(ab - nmB);
        smB = smB * scB + w1;
        a0B = a0B * scB + w1 * f10;
        a1B = a1B * scB + w1 * f11;
        mxB = nmB;
    }
    if (j < end) {
        int s0 = g_csrc[j];
        float es0 = g_esrc2[s0];
        const float* h0 = g_h2 + (size_t)s0 * NC;
        float f00 = h0[lane];
        float f01 = (lane < 8) ? h0[32 + lane] : 0.f;
        float aa = lrelu(es0 + ed);
        float nmA = fmaxf(mxA, aa);
        float scA = __expf(mxA - nmA);
        float w0  = __expf(aa - nmA);
        smA = smA * scA + w0;
        a0A = a0A * scA + w0 * f00;
        a1A = a1A * scA + w0 * f01;
        mxA = nmA;
    }
    float nm = fmaxf(mxA, mxB);
    float sA = __expf(mxA - nm);
    float sB = __expf(mxB - nm);
    float sum = smA * sA + smB * sB;
    float acc0 = a0A * sA + a0B * sB;
    float acc1 = a1A * sA + a1B * sB;
    float inv = 1.0f / (sum + 1e-16f);

    float v0 = acc0 * inv + __ldg(bias + lane);
    float v1 = (lane < 8) ? (acc1 * inv + __ldg(bias + 32 + lane)) : -INFINITY;
    float m = fmaxf(v0, v1);
    #pragma unroll
    for (int o = 16; o >= 1; o >>= 1) m = fmaxf(m, __shfl_xor_sync(0xffffffffu, m, o));
    float e0 = expf(v0 - m);
    float e1 = (lane < 8) ? expf(v1 - m) : 0.f;
    float sm = e0 + e1;
    #pragma unroll
    for (int o = 16; o >= 1; o >>= 1) sm += __shfl_xor_sync(0xffffffffu, sm, o);
    float ls = logf(sm);
    float invs = 1.0f / sm;
    float* lo = out + (size_t)d * NC;
    float* so = out + (size_t)NN * NC + (size_t)d * NC;
    lo[lane] = v0 - m - ls;
    so[lane] = e0 * invs;
    if (lane < 8) {
        lo[32 + lane] = v1 - m - ls;
        so[32 + lane] = e1 * invs;
    }
}

// ---------------- launch ----------------
extern "C" void kernel_launch(void* const* d_in, const int* in_sizes, int n_in,
                              void* d_out, int out_size) {
    const float* x   = (const float*)d_in[0];
    const int*   ei  = (const int*)d_in[1];
    const float* W1  = (const float*)d_in[2];
    const float* as1 = (const float*)d_in[3];
    const float* ad1 = (const float*)d_in[4];
    const float* b1  = (const float*)d_in[5];
    const float* W2  = (const float*)d_in[6];
    const float* as2 = (const float*)d_in[7];
    const float* ad2 = (const float*)d_in[8];
    const float* b2  = (const float*)d_in[9];
    float* out = (float*)d_out;
    const int* src = ei;
    const int* dst = ei + NE;

    hist_kernel<<<3125, 256>>>(dst);
    scan1_kernel<<<NBLK, 256>>>();
    scan3_kernel<<<NBLK, 256>>>();
    place_kernel<<<3125, 256>>>(src, dst);
    gemm1_kernel<<<782, 256>>>(x, W1, as1, ad1);
    gat1_kernel<<<6250, 256>>>(b1);
    gemm2_kernel<<<782, 256>>>(W2, as2, ad2);
    gat2_kernel<<<6250, 256>>>(b2, out);
}